// round 1
// baseline (speedup 1.0000x reference)
#include <cuda_runtime.h>
#include <math.h>

#define L_TOT 13824
#define CL    96
#define NCH   144
#define DM    128
#define NST   16
#define DTRK  8

// ---------------- device scratch (static, no allocations) ----------------
__device__ float g_buf[2][L_TOT * DM];   // ping-pong xc buffers [S][128]
__device__ float g_z[L_TOT * DM];        // silu(z)
__device__ float g_xp[L_TOT * DM];       // pre-conv x part
__device__ float g_dt[L_TOT * DM];       // per-direction dt scratch
__device__ float g_bc[L_TOT * 32];       // per-direction B(16)+C(16) scratch
__device__ float g_Ach[NCH * 2048];      // chunk aggregate: prod(dA)
__device__ float g_Bch[NCH * 2048];      // chunk aggregate: local final h
__device__ float g_Hpref[NCH * 2048];    // exclusive prefix h0 per chunk

__device__ __forceinline__ float siluf(float v) {
    return v / (1.f + __expf(-v));
}
__device__ __forceinline__ float softplusf(float x) {
    if (x > 20.f) return x;
    return log1pf(__expf(x));
}

// sequence position -> spatial index (h*576 + w*24 + d), flip folded in
template<int DIR>
__device__ __forceinline__ int seq_to_spatial(int l) {
    if (DIR & 1) l = L_TOT - 1 - l;
    int i0 = l % 24;
    int t  = l / 24;
    int i1 = t % 24;
    int i2 = t / 24;
    switch (DIR >> 1) {
        case 0:  return i1 * 576 + i2 * 24 + i0;  // (w,h,d) order
        case 1:  return i2 * 576 + i1 * 24 + i0;  // (h,w,d)
        case 2:  return i0 * 576 + i1 * 24 + i2;  // (d,w,h)
        default: return i2 * 576 + i0 * 24 + i1;  // (h,d,w)
    }
}

// ---------------- K0: in_proj (xz = x @ W^T), split into xp / silu(z) ----
__global__ void __launch_bounds__(256) k_inproj(const float* __restrict__ x,
                                                const float* __restrict__ Win) {
    const int ST = 24;
    __shared__ float xs[ST * DM];
    int s0 = blockIdx.x * ST;
    for (int j = threadIdx.x; j < ST * DM; j += 256) xs[j] = x[s0 * DM + j];
    __syncthreads();
    int e = threadIdx.x;            // output feature 0..255
    float acc[ST];
#pragma unroll
    for (int i = 0; i < ST; i++) acc[i] = 0.f;
    const float4* w4 = (const float4*)(Win + e * DM);
    for (int k4 = 0; k4 < DM / 4; k4++) {
        float4 w = w4[k4];
#pragma unroll
        for (int i = 0; i < ST; i++) {
            float4 xv = *(const float4*)(xs + i * DM + k4 * 4);
            acc[i] = fmaf(w.x, xv.x, fmaf(w.y, xv.y, fmaf(w.z, xv.z, fmaf(w.w, xv.w, acc[i]))));
        }
    }
    if (e < DM) {
#pragma unroll
        for (int i = 0; i < ST; i++) g_xp[(s0 + i) * DM + e] = acc[i];
    } else {
        int c = e - DM;
#pragma unroll
        for (int i = 0; i < ST; i++) g_z[(s0 + i) * DM + c] = siluf(acc[i]);
    }
}

// ---------------- K0b: depthwise 3x3x3 conv + bias + silu ----------------
__global__ void __launch_bounds__(512) k_conv(const float* __restrict__ cw,
                                              const float* __restrict__ cb) {
    __shared__ float cws[DM * 27];
    int tid = threadIdx.x;
    for (int j = tid; j < DM * 27; j += 512) cws[j] = cw[j];
    __syncthreads();
    int c = tid & 127;
    int s = blockIdx.x * 4 + (tid >> 7);
    int d0 = s % 24, t = s / 24, w0 = t % 24, h0 = t / 24;
    float acc = cb[c];
#pragma unroll
    for (int kh = 0; kh < 3; kh++) {
        int hh = h0 + kh - 1; if ((unsigned)hh >= 24u) continue;
#pragma unroll
        for (int kw = 0; kw < 3; kw++) {
            int ww = w0 + kw - 1; if ((unsigned)ww >= 24u) continue;
#pragma unroll
            for (int kd = 0; kd < 3; kd++) {
                int dd = d0 + kd - 1; if ((unsigned)dd >= 24u) continue;
                acc = fmaf(cws[c * 27 + kh * 9 + kw * 3 + kd],
                           g_xp[((hh * 24 + ww) * 24 + dd) * DM + c], acc);
            }
        }
    }
    g_buf[0][s * DM + c] = siluf(acc);
}

// ---------------- K1: chunk local scan + x_dbl matmul --------------------
// smem layout: u_s[128][97] | xd_s[40][97] | W_s[40][128]
template<int DIR>
__global__ void __launch_bounds__(128) k_scan1(const float* __restrict__ xproj_w,
                                               const float* __restrict__ dtw_g,
                                               const float* __restrict__ dtb_g,
                                               const float* __restrict__ Alog_g) {
    extern __shared__ float sm[];
    float* u_s  = sm;                    // [128][97]
    float* xd_s = sm + 128 * 97;         // [40][97]
    float* W_s  = xd_s + 40 * 97;        // [40][128]
    const int tid = threadIdx.x;
    const int ci  = blockIdx.x;
    const int lbase = ci * CL;
    const float* __restrict__ xin = g_buf[DIR & 1];

    // load x_proj weights (40 x 128)
    for (int j = tid; j < 40 * DM; j += 128) W_s[j] = xproj_w[DIR * 40 * DM + j];
    // gather u chunk (coalesced per l)
#pragma unroll 4
    for (int l = 0; l < CL; l++) {
        int sp = seq_to_spatial<DIR>(lbase + l);
        u_s[tid * 97 + l] = xin[sp * DM + tid];
    }
    __syncthreads();

    // x_dbl = W (40x128) @ u (128x96), register-tiled 10c x 3l per thread
    {
        int c0 = (tid >> 5) * 10;
        int l0 = (tid & 31) * 3;
        float acc[10][3];
#pragma unroll
        for (int i = 0; i < 10; i++)
#pragma unroll
            for (int j = 0; j < 3; j++) acc[i][j] = 0.f;
        for (int k = 0; k < DM; k++) {
            float u0 = u_s[k * 97 + l0];
            float u1 = u_s[k * 97 + l0 + 1];
            float u2 = u_s[k * 97 + l0 + 2];
#pragma unroll
            for (int i = 0; i < 10; i++) {
                float w = W_s[(c0 + i) * DM + k];
                acc[i][0] = fmaf(w, u0, acc[i][0]);
                acc[i][1] = fmaf(w, u1, acc[i][1]);
                acc[i][2] = fmaf(w, u2, acc[i][2]);
            }
        }
#pragma unroll
        for (int i = 0; i < 10; i++)
#pragma unroll
            for (int j = 0; j < 3; j++) xd_s[(c0 + i) * 97 + l0 + j] = acc[i][j];
    }
    __syncthreads();

    // per-thread constants (thread = channel d)
    float dtw[DTRK];
#pragma unroll
    for (int r = 0; r < DTRK; r++) dtw[r] = dtw_g[DIR * DM * DTRK + tid * DTRK + r];
    float bias = dtb_g[DIR * DM + tid];
    float A_[NST];
#pragma unroll
    for (int n = 0; n < NST; n++) A_[n] = -__expf(Alog_g[(DIR * DM + tid) * NST + n]);

    float h[NST], P[NST];
#pragma unroll
    for (int n = 0; n < NST; n++) { h[n] = 0.f; P[n] = 1.f; }

    for (int l = 0; l < CL; l++) {
        float dtr = bias;
#pragma unroll
        for (int r = 0; r < DTRK; r++) dtr = fmaf(dtw[r], xd_s[r * 97 + l], dtr);
        float dt = softplusf(dtr);
        g_dt[(lbase + l) * DM + tid] = dt;
        float dtu = dt * u_s[tid * 97 + l];
#pragma unroll
        for (int n = 0; n < NST; n++) {
            float a = __expf(A_[n] * dt);
            h[n] = fmaf(a, h[n], dtu * xd_s[(8 + n) * 97 + l]);
            P[n] *= a;
        }
    }
#pragma unroll
    for (int n = 0; n < NST; n++) {
        g_Ach[ci * 2048 + tid * NST + n] = P[n];
        g_Bch[ci * 2048 + tid * NST + n] = h[n];
    }
    // store B,C rows to global (coalesced)
    for (int j = tid; j < CL * 32; j += 128) {
        int l = j >> 5, n = j & 31;
        g_bc[(lbase + l) * 32 + n] = xd_s[(8 + n) * 97 + l];
    }
}

// ---------------- K2: exclusive prefix over chunk aggregates -------------
__global__ void __launch_bounds__(256) k_prefix() {
    int i = blockIdx.x * 256 + threadIdx.x;  // 0..2047
    float h = 0.f;
#pragma unroll 4
    for (int c = 0; c < NCH; c++) {
        g_Hpref[c * 2048 + i] = h;
        float a = g_Ach[c * 2048 + i];
        float b = g_Bch[c * 2048 + i];
        h = fmaf(a, h, b);
    }
}

// ---------------- K3: seeded re-scan + output ----------------------------
// smem layout: u_s[128][97] | dt_s[128][97] | bc_s[96][32]
template<int DIR>
__global__ void __launch_bounds__(128) k_scan2(const float* __restrict__ Alog_g,
                                               const float* __restrict__ Ds_g) {
    extern __shared__ float sm[];
    float* u_s  = sm;                 // [128][97]
    float* dt_s = sm + 128 * 97;      // [128][97]
    float* bc_s = dt_s + 128 * 97;    // [96][32]
    const int tid = threadIdx.x;
    const int ci  = blockIdx.x;
    const int lbase = ci * CL;
    const float* __restrict__ xin = g_buf[DIR & 1];
    float* __restrict__ xout = g_buf[(DIR + 1) & 1];

#pragma unroll 4
    for (int l = 0; l < CL; l++) {
        int sp = seq_to_spatial<DIR>(lbase + l);
        u_s[tid * 97 + l]  = xin[sp * DM + tid];
        dt_s[tid * 97 + l] = g_dt[(lbase + l) * DM + tid];
    }
    for (int j = tid; j < CL * 32; j += 128) bc_s[j] = g_bc[lbase * 32 + j];
    __syncthreads();

    float A_[NST];
#pragma unroll
    for (int n = 0; n < NST; n++) A_[n] = -__expf(Alog_g[(DIR * DM + tid) * NST + n]);
    float Dv = Ds_g[DIR * DM + tid];
    float h[NST];
#pragma unroll
    for (int n = 0; n < NST; n++) h[n] = g_Hpref[ci * 2048 + tid * NST + n];

    for (int l = 0; l < CL; l++) {
        int sp = seq_to_spatial<DIR>(lbase + l);
        float dt = dt_s[tid * 97 + l];
        float u  = u_s[tid * 97 + l];
        float dtu = dt * u;
        float y = u * Dv;
#pragma unroll
        for (int n = 0; n < NST; n++) {
            float a = __expf(A_[n] * dt);
            h[n] = fmaf(a, h[n], dtu * bc_s[l * 32 + n]);
            y = fmaf(h[n], bc_s[l * 32 + 16 + n], y);
        }
        xout[sp * DM + tid] = y;
    }
}

// ---------------- K4: LayerNorm + gate + out_proj ------------------------
// smem: ym[16][132] | Wt[128][129]
__global__ void __launch_bounds__(128) k_final(const float* __restrict__ gamma,
                                               const float* __restrict__ beta,
                                               const float* __restrict__ Wout,
                                               float* __restrict__ out) {
    extern __shared__ float sm[];
    float* ym = sm;                   // [16][132]
    float* Wt = sm + 16 * 132;        // [128][129] transposed W
    __shared__ float mu_s[16], rs_s[16];
    const int tid = threadIdx.x;
    const int s0 = blockIdx.x * 16;

    for (int j = tid; j < 16 * DM; j += 128) {
        int si = j >> 7, c = j & 127;
        ym[si * 132 + c] = g_buf[0][(s0 + si) * DM + c];
    }
    for (int j = tid; j < DM * DM; j += 128) {
        int c = j >> 7, e = j & 127;
        Wt[e * 129 + c] = Wout[j];
    }
    __syncthreads();

    if (tid < 16) {
        float m = 0.f;
        for (int c = 0; c < DM; c++) m += ym[tid * 132 + c];
        m *= (1.f / DM);
        float v = 0.f;
        for (int c = 0; c < DM; c++) { float d = ym[tid * 132 + c] - m; v = fmaf(d, d, v); }
        v *= (1.f / DM);
        mu_s[tid] = m;
        rs_s[tid] = rsqrtf(v + 1e-5f);
    }
    __syncthreads();

    for (int j = tid; j < 16 * DM; j += 128) {
        int si = j >> 7, c = j & 127;
        float v = (ym[si * 132 + c] - mu_s[si]) * rs_s[si] * gamma[c] + beta[c];
        ym[si * 132 + c] = v * g_z[(s0 + si) * DM + c];
    }
    __syncthreads();

    float acc[16];
#pragma unroll
    for (int i = 0; i < 16; i++) acc[i] = 0.f;
    for (int e4 = 0; e4 < DM / 4; e4++) {
        float w0 = Wt[(e4 * 4 + 0) * 129 + tid];
        float w1 = Wt[(e4 * 4 + 1) * 129 + tid];
        float w2 = Wt[(e4 * 4 + 2) * 129 + tid];
        float w3 = Wt[(e4 * 4 + 3) * 129 + tid];
#pragma unroll
        for (int si = 0; si < 16; si++) {
            float4 yv = *(const float4*)(ym + si * 132 + e4 * 4);
            acc[si] = fmaf(w0, yv.x, fmaf(w1, yv.y, fmaf(w2, yv.z, fmaf(w3, yv.w, acc[si]))));
        }
    }
#pragma unroll
    for (int si = 0; si < 16; si++) out[(s0 + si) * DM + tid] = acc[si];
}

// ---------------- launch ----------------
#define SM1 ((128 * 97 + 40 * 97 + 40 * 128) * 4)
#define SM3 ((128 * 97 + 128 * 97 + 96 * 32) * 4)
#define SM4 ((16 * 132 + 128 * 129) * 4)

extern "C" void kernel_launch(void* const* d_in, const int* in_sizes, int n_in,
                              void* d_out, int out_size) {
    const float* x         = (const float*)d_in[0];
    const float* in_proj_w = (const float*)d_in[1];
    const float* conv_w    = (const float*)d_in[2];
    const float* conv_b    = (const float*)d_in[3];
    const float* xproj_w   = (const float*)d_in[4];
    const float* dtw       = (const float*)d_in[5];
    const float* dtb       = (const float*)d_in[6];
    const float* A_logs    = (const float*)d_in[7];
    const float* Ds        = (const float*)d_in[8];
    const float* ln_g      = (const float*)d_in[9];
    const float* ln_b      = (const float*)d_in[10];
    const float* out_w     = (const float*)d_in[11];
    float* out = (float*)d_out;

    cudaFuncSetAttribute(k_scan1<0>, cudaFuncAttributeMaxDynamicSharedMemorySize, SM1);
    cudaFuncSetAttribute(k_scan1<1>, cudaFuncAttributeMaxDynamicSharedMemorySize, SM1);
    cudaFuncSetAttribute(k_scan1<2>, cudaFuncAttributeMaxDynamicSharedMemorySize, SM1);
    cudaFuncSetAttribute(k_scan1<3>, cudaFuncAttributeMaxDynamicSharedMemorySize, SM1);
    cudaFuncSetAttribute(k_scan1<4>, cudaFuncAttributeMaxDynamicSharedMemorySize, SM1);
    cudaFuncSetAttribute(k_scan1<5>, cudaFuncAttributeMaxDynamicSharedMemorySize, SM1);
    cudaFuncSetAttribute(k_scan1<6>, cudaFuncAttributeMaxDynamicSharedMemorySize, SM1);
    cudaFuncSetAttribute(k_scan1<7>, cudaFuncAttributeMaxDynamicSharedMemorySize, SM1);
    cudaFuncSetAttribute(k_scan2<0>, cudaFuncAttributeMaxDynamicSharedMemorySize, SM3);
    cudaFuncSetAttribute(k_scan2<1>, cudaFuncAttributeMaxDynamicSharedMemorySize, SM3);
    cudaFuncSetAttribute(k_scan2<2>, cudaFuncAttributeMaxDynamicSharedMemorySize, SM3);
    cudaFuncSetAttribute(k_scan2<3>, cudaFuncAttributeMaxDynamicSharedMemorySize, SM3);
    cudaFuncSetAttribute(k_scan2<4>, cudaFuncAttributeMaxDynamicSharedMemorySize, SM3);
    cudaFuncSetAttribute(k_scan2<5>, cudaFuncAttributeMaxDynamicSharedMemorySize, SM3);
    cudaFuncSetAttribute(k_scan2<6>, cudaFuncAttributeMaxDynamicSharedMemorySize, SM3);
    cudaFuncSetAttribute(k_scan2<7>, cudaFuncAttributeMaxDynamicSharedMemorySize, SM3);
    cudaFuncSetAttribute(k_final,    cudaFuncAttributeMaxDynamicSharedMemorySize, SM4);

    k_inproj<<<L_TOT / 24, 256>>>(x, in_proj_w);
    k_conv<<<L_TOT / 4, 512>>>(conv_w, conv_b);

#define DIR_ROUND(D)                                                   \
    k_scan1<D><<<NCH, 128, SM1>>>(xproj_w, dtw, dtb, A_logs);          \
    k_prefix<<<8, 256>>>();                                            \
    k_scan2<D><<<NCH, 128, SM3>>>(A_logs, Ds);

    DIR_ROUND(0)
    DIR_ROUND(1)
    DIR_ROUND(2)
    DIR_ROUND(3)
    DIR_ROUND(4)
    DIR_ROUND(5)
    DIR_ROUND(6)
    DIR_ROUND(7)
#undef DIR_ROUND

    k_final<<<L_TOT / 16, 128, SM4>>>(ln_g, ln_b, out_w, out);
}

// round 2
// speedup vs baseline: 1.8654x; 1.8654x over previous
#include <cuda_runtime.h>
#include <math.h>

#define L_TOT 13824
#define CL    96
#define NCH   144
#define DM    128
#define NST   16
#define DTRK  8

// ---------------- device scratch (static, no allocations) ----------------
__device__ float g_buf[2][L_TOT * DM];   // ping-pong xc buffers [S][128]
__device__ float g_z[L_TOT * DM];        // silu(z)
__device__ float g_xp[L_TOT * DM];       // pre-conv x part
__device__ float g_dt[L_TOT * DM];       // per-direction dt scratch
__device__ float g_bc[L_TOT * 32];       // per-direction B(16)+C(16) scratch
__device__ float g_Ach[2048 * NCH];      // chunk aggregate prod(dA), [lane][chunk]
__device__ float g_Bch[2048 * NCH];      // chunk aggregate local h,  [lane][chunk]
__device__ float g_Hpref[2048 * NCH];    // exclusive prefix h0,      [lane][chunk]

__device__ __forceinline__ float siluf(float v) {
    return v / (1.f + __expf(-v));
}
__device__ __forceinline__ float softplusf(float x) {
    if (x > 20.f) return x;
    return __logf(1.f + __expf(x));
}

// sequence position -> spatial index (h*576 + w*24 + d), flip folded in
template<int DIR>
__device__ __forceinline__ int seq_to_spatial(int l) {
    if (DIR & 1) l = L_TOT - 1 - l;
    int i0 = l % 24;
    int t  = l / 24;
    int i1 = t % 24;
    int i2 = t / 24;
    switch (DIR >> 1) {
        case 0:  return i1 * 576 + i2 * 24 + i0;
        case 1:  return i2 * 576 + i1 * 24 + i0;
        case 2:  return i0 * 576 + i1 * 24 + i2;
        default: return i2 * 576 + i0 * 24 + i1;
    }
}

// powers a[n] = e1^(n+1), n = 0..15, via binary tree (depth 4)
__device__ __forceinline__ void pow16(float e1, float* av) {
    float e2 = e1 * e1, e4 = e2 * e2, e8 = e4 * e4;
    av[0] = e1;       av[1] = e2;       av[2] = e2 * e1;   av[3] = e4;
    av[4] = e4 * e1;  av[5] = e4 * e2;  av[6] = e4 * av[2]; av[7] = e8;
    av[8] = e8 * e1;  av[9] = e8 * e2;  av[10] = e8 * av[2]; av[11] = e8 * e4;
    av[12] = e8 * av[4]; av[13] = e8 * av[5]; av[14] = e8 * av[6]; av[15] = e8 * e8;
}

// ---------------- K0: in_proj (xz = x @ W^T), split into xp / silu(z) ----
__global__ void __launch_bounds__(256) k_inproj(const float* __restrict__ x,
                                                const float* __restrict__ Win) {
    const int ST = 24;
    __shared__ float xs[ST * DM];
    int s0 = blockIdx.x * ST;
    for (int j = threadIdx.x; j < ST * DM; j += 256) xs[j] = x[s0 * DM + j];
    __syncthreads();
    int e = threadIdx.x;
    float acc[ST];
#pragma unroll
    for (int i = 0; i < ST; i++) acc[i] = 0.f;
    const float4* w4 = (const float4*)(Win + e * DM);
    for (int k4 = 0; k4 < DM / 4; k4++) {
        float4 w = w4[k4];
#pragma unroll
        for (int i = 0; i < ST; i++) {
            float4 xv = *(const float4*)(xs + i * DM + k4 * 4);
            acc[i] = fmaf(w.x, xv.x, fmaf(w.y, xv.y, fmaf(w.z, xv.z, fmaf(w.w, xv.w, acc[i]))));
        }
    }
    if (e < DM) {
#pragma unroll
        for (int i = 0; i < ST; i++) g_xp[(s0 + i) * DM + e] = acc[i];
    } else {
        int c = e - DM;
#pragma unroll
        for (int i = 0; i < ST; i++) g_z[(s0 + i) * DM + c] = siluf(acc[i]);
    }
}

// ---------------- K0b: depthwise 3x3x3 conv + bias + silu ----------------
__global__ void __launch_bounds__(512) k_conv(const float* __restrict__ cw,
                                              const float* __restrict__ cb) {
    __shared__ float cws[DM * 27];
    int tid = threadIdx.x;
    for (int j = tid; j < DM * 27; j += 512) cws[j] = cw[j];
    __syncthreads();
    int c = tid & 127;
    int s = blockIdx.x * 4 + (tid >> 7);
    int d0 = s % 24, t = s / 24, w0 = t % 24, h0 = t / 24;
    float acc = cb[c];
#pragma unroll
    for (int kh = 0; kh < 3; kh++) {
        int hh = h0 + kh - 1; if ((unsigned)hh >= 24u) continue;
#pragma unroll
        for (int kw = 0; kw < 3; kw++) {
            int ww = w0 + kw - 1; if ((unsigned)ww >= 24u) continue;
#pragma unroll
            for (int kd = 0; kd < 3; kd++) {
                int dd = d0 + kd - 1; if ((unsigned)dd >= 24u) continue;
                acc = fmaf(cws[c * 27 + kh * 9 + kw * 3 + kd],
                           g_xp[((hh * 24 + ww) * 24 + dd) * DM + c], acc);
            }
        }
    }
    g_buf[0][s * DM + c] = siluf(acc);
}

// ---------------- K1: chunk local scan + x_dbl matmul --------------------
template<int DIR>
__global__ void __launch_bounds__(128) k_scan1(const float* __restrict__ xproj_w,
                                               const float* __restrict__ dtw_g,
                                               const float* __restrict__ dtb_g,
                                               const float* __restrict__ Alog_g) {
    extern __shared__ float sm[];
    float* u_s  = sm;                    // [128][97]
    float* xd_s = sm + 128 * 97;         // [40][97]
    float* W_s  = xd_s + 40 * 97;        // [40][128]
    const int tid = threadIdx.x;
    const int ci  = blockIdx.x;
    const int lbase = ci * CL;
    const float* __restrict__ xin = g_buf[DIR & 1];

    for (int j = tid; j < 40 * DM; j += 128) W_s[j] = xproj_w[DIR * 40 * DM + j];
#pragma unroll 4
    for (int l = 0; l < CL; l++) {
        int sp = seq_to_spatial<DIR>(lbase + l);
        u_s[tid * 97 + l] = xin[sp * DM + tid];
    }
    __syncthreads();

    // x_dbl = W (40x128) @ u (128x96)
    {
        int c0 = (tid >> 5) * 10;
        int l0 = (tid & 31) * 3;
        float acc[10][3];
#pragma unroll
        for (int i = 0; i < 10; i++)
#pragma unroll
            for (int j = 0; j < 3; j++) acc[i][j] = 0.f;
        for (int k = 0; k < DM; k++) {
            float u0 = u_s[k * 97 + l0];
            float u1 = u_s[k * 97 + l0 + 1];
            float u2 = u_s[k * 97 + l0 + 2];
#pragma unroll
            for (int i = 0; i < 10; i++) {
                float w = W_s[(c0 + i) * DM + k];
                acc[i][0] = fmaf(w, u0, acc[i][0]);
                acc[i][1] = fmaf(w, u1, acc[i][1]);
                acc[i][2] = fmaf(w, u2, acc[i][2]);
            }
        }
#pragma unroll
        for (int i = 0; i < 10; i++)
#pragma unroll
            for (int j = 0; j < 3; j++) xd_s[(c0 + i) * 97 + l0 + j] = acc[i][j];
    }
    __syncthreads();

    float dtw[DTRK];
#pragma unroll
    for (int r = 0; r < DTRK; r++) dtw[r] = dtw_g[DIR * DM * DTRK + tid * DTRK + r];
    float bias = dtb_g[DIR * DM + tid];
    float A_[NST];
#pragma unroll
    for (int n = 0; n < NST; n++) A_[n] = -__expf(Alog_g[(DIR * DM + tid) * NST + n]);
    float A0 = A_[0];
    bool fast = true;
#pragma unroll
    for (int n = 0; n < NST; n++)
        if (fabsf(A_[n] - (float)(n + 1) * A0) > 1e-5f * fabsf(A_[n])) fast = false;

    float h[NST];
#pragma unroll
    for (int n = 0; n < NST; n++) h[n] = 0.f;
    float sdt = 0.f;

    if (fast) {
        for (int l = 0; l < CL; l++) {
            float dtr = bias;
#pragma unroll
            for (int r = 0; r < DTRK; r++) dtr = fmaf(dtw[r], xd_s[r * 97 + l], dtr);
            float dt = softplusf(dtr);
            g_dt[(lbase + l) * DM + tid] = dt;
            sdt += dt;
            float dtu = dt * u_s[tid * 97 + l];
            float av[NST];
            pow16(__expf(A0 * dt), av);
#pragma unroll
            for (int n = 0; n < NST; n++)
                h[n] = fmaf(av[n], h[n], dtu * xd_s[(8 + n) * 97 + l]);
        }
    } else {
        for (int l = 0; l < CL; l++) {
            float dtr = bias;
#pragma unroll
            for (int r = 0; r < DTRK; r++) dtr = fmaf(dtw[r], xd_s[r * 97 + l], dtr);
            float dt = softplusf(dtr);
            g_dt[(lbase + l) * DM + tid] = dt;
            sdt += dt;
            float dtu = dt * u_s[tid * 97 + l];
#pragma unroll
            for (int n = 0; n < NST; n++)
                h[n] = fmaf(__expf(A_[n] * dt), h[n], dtu * xd_s[(8 + n) * 97 + l]);
        }
    }
    // chunk aggregates: P = exp(A_n * sum(dt)) == prod(exp(A_n dt))
#pragma unroll
    for (int n = 0; n < NST; n++) {
        g_Ach[(tid * NST + n) * NCH + ci] = __expf(A_[n] * sdt);
        g_Bch[(tid * NST + n) * NCH + ci] = h[n];
    }
    for (int j = tid; j < CL * 32; j += 128) {
        int l = j >> 5, n = j & 31;
        g_bc[(lbase + l) * 32 + n] = xd_s[(8 + n) * 97 + l];
    }
}

// ---------------- K2: warp-parallel exclusive scan over chunk aggregates --
// one warp per (d,n) lane: 2048 warps, 5 chunks/thread, shfl affine-compose scan
__global__ void __launch_bounds__(256) k_prefix() {
    int gw   = (blockIdx.x * 256 + threadIdx.x) >> 5;   // lane id 0..2047
    int lane = threadIdx.x & 31;
    const float* Aa = g_Ach + gw * NCH;
    const float* Bb = g_Bch + gw * NCH;
    float* Hp = g_Hpref + gw * NCH;

    float a_loc[5], b_loc[5];
    float Ag = 1.f, Bg = 0.f;
    int c0 = lane * 5;
#pragma unroll
    for (int k = 0; k < 5; k++) {
        int c = c0 + k;
        float a = 1.f, b = 0.f;
        if (c < NCH) { a = Aa[c]; b = Bb[c]; }
        a_loc[k] = a; b_loc[k] = b;
        Bg = fmaf(a, Bg, b);
        Ag *= a;
    }
#pragma unroll
    for (int d = 1; d < 32; d <<= 1) {
        float aL = __shfl_up_sync(0xffffffffu, Ag, d);
        float bL = __shfl_up_sync(0xffffffffu, Bg, d);
        if (lane >= d) { Bg = fmaf(Ag, bL, Bg); Ag *= aL; }
    }
    float hp = __shfl_up_sync(0xffffffffu, Bg, 1);
    float h = (lane == 0) ? 0.f : hp;
#pragma unroll
    for (int k = 0; k < 5; k++) {
        int c = c0 + k;
        if (c < NCH) Hp[c] = h;
        h = fmaf(a_loc[k], h, b_loc[k]);
    }
}

// ---------------- K3: seeded re-scan + output ----------------------------
template<int DIR>
__global__ void __launch_bounds__(128) k_scan2(const float* __restrict__ Alog_g,
                                               const float* __restrict__ Ds_g) {
    extern __shared__ float sm[];
    float* u_s  = sm;                 // [128][97]
    float* dt_s = sm + 128 * 97;      // [128][97]
    float* bc_s = dt_s + 128 * 97;    // [96][32]
    const int tid = threadIdx.x;
    const int ci  = blockIdx.x;
    const int lbase = ci * CL;
    const float* __restrict__ xin = g_buf[DIR & 1];
    float* __restrict__ xout = g_buf[(DIR + 1) & 1];

#pragma unroll 4
    for (int l = 0; l < CL; l++) {
        int sp = seq_to_spatial<DIR>(lbase + l);
        u_s[tid * 97 + l]  = xin[sp * DM + tid];
        dt_s[tid * 97 + l] = g_dt[(lbase + l) * DM + tid];
    }
    for (int j = tid; j < CL * 32; j += 128) bc_s[j] = g_bc[lbase * 32 + j];
    __syncthreads();

    float A_[NST];
#pragma unroll
    for (int n = 0; n < NST; n++) A_[n] = -__expf(Alog_g[(DIR * DM + tid) * NST + n]);
    float A0 = A_[0];
    bool fast = true;
#pragma unroll
    for (int n = 0; n < NST; n++)
        if (fabsf(A_[n] - (float)(n + 1) * A0) > 1e-5f * fabsf(A_[n])) fast = false;
    float Dv = Ds_g[DIR * DM + tid];
    float h[NST];
#pragma unroll
    for (int n = 0; n < NST; n++) h[n] = g_Hpref[(tid * NST + n) * NCH + ci];

    if (fast) {
        for (int l = 0; l < CL; l++) {
            int sp = seq_to_spatial<DIR>(lbase + l);
            float dt = dt_s[tid * 97 + l];
            float u  = u_s[tid * 97 + l];
            float dtu = dt * u;
            float y = u * Dv;
            float av[NST];
            pow16(__expf(A0 * dt), av);
#pragma unroll
            for (int n = 0; n < NST; n++) {
                h[n] = fmaf(av[n], h[n], dtu * bc_s[l * 32 + n]);
                y = fmaf(h[n], bc_s[l * 32 + 16 + n], y);
            }
            xout[sp * DM + tid] = y;
        }
    } else {
        for (int l = 0; l < CL; l++) {
            int sp = seq_to_spatial<DIR>(lbase + l);
            float dt = dt_s[tid * 97 + l];
            float u  = u_s[tid * 97 + l];
            float dtu = dt * u;
            float y = u * Dv;
#pragma unroll
            for (int n = 0; n < NST; n++) {
                h[n] = fmaf(__expf(A_[n] * dt), h[n], dtu * bc_s[l * 32 + n]);
                y = fmaf(h[n], bc_s[l * 32 + 16 + n], y);
            }
            xout[sp * DM + tid] = y;
        }
    }
}

// ---------------- K4: LayerNorm + gate + out_proj ------------------------
__global__ void __launch_bounds__(128) k_final(const float* __restrict__ gamma,
                                               const float* __restrict__ beta,
                                               const float* __restrict__ Wout,
                                               float* __restrict__ out) {
    extern __shared__ float sm[];
    float* ym = sm;                   // [16][132]
    float* Wt = sm + 16 * 132;        // [128][129]
    __shared__ float mu_s[16], rs_s[16];
    const int tid = threadIdx.x;
    const int s0 = blockIdx.x * 16;

    for (int j = tid; j < 16 * DM; j += 128) {
        int si = j >> 7, c = j & 127;
        ym[si * 132 + c] = g_buf[0][(s0 + si) * DM + c];
    }
    for (int j = tid; j < DM * DM; j += 128) {
        int c = j >> 7, e = j & 127;
        Wt[e * 129 + c] = Wout[j];
    }
    __syncthreads();

    if (tid < 16) {
        float m = 0.f;
        for (int c = 0; c < DM; c++) m += ym[tid * 132 + c];
        m *= (1.f / DM);
        float v = 0.f;
        for (int c = 0; c < DM; c++) { float d = ym[tid * 132 + c] - m; v = fmaf(d, d, v); }
        v *= (1.f / DM);
        mu_s[tid] = m;
        rs_s[tid] = rsqrtf(v + 1e-5f);
    }
    __syncthreads();

    for (int j = tid; j < 16 * DM; j += 128) {
        int si = j >> 7, c = j & 127;
        float v = (ym[si * 132 + c] - mu_s[si]) * rs_s[si] * gamma[c] + beta[c];
        ym[si * 132 + c] = v * g_z[(s0 + si) * DM + c];
    }
    __syncthreads();

    float acc[16];
#pragma unroll
    for (int i = 0; i < 16; i++) acc[i] = 0.f;
    for (int e4 = 0; e4 < DM / 4; e4++) {
        float w0 = Wt[(e4 * 4 + 0) * 129 + tid];
        float w1 = Wt[(e4 * 4 + 1) * 129 + tid];
        float w2 = Wt[(e4 * 4 + 2) * 129 + tid];
        float w3 = Wt[(e4 * 4 + 3) * 129 + tid];
#pragma unroll
        for (int si = 0; si < 16; si++) {
            float4 yv = *(const float4*)(ym + si * 132 + e4 * 4);
            acc[si] = fmaf(w0, yv.x, fmaf(w1, yv.y, fmaf(w2, yv.z, fmaf(w3, yv.w, acc[si]))));
        }
    }
#pragma unroll
    for (int si = 0; si < 16; si++) out[(s0 + si) * DM + tid] = acc[si];
}

// ---------------- launch ----------------
#define SM1 ((128 * 97 + 40 * 97 + 40 * 128) * 4)
#define SM3 ((128 * 97 + 128 * 97 + 96 * 32) * 4)
#define SM4 ((16 * 132 + 128 * 129) * 4)

extern "C" void kernel_launch(void* const* d_in, const int* in_sizes, int n_in,
                              void* d_out, int out_size) {
    const float* x         = (const float*)d_in[0];
    const float* in_proj_w = (const float*)d_in[1];
    const float* conv_w    = (const float*)d_in[2];
    const float* conv_b    = (const float*)d_in[3];
    const float* xproj_w   = (const float*)d_in[4];
    const float* dtw       = (const float*)d_in[5];
    const float* dtb       = (const float*)d_in[6];
    const float* A_logs    = (const float*)d_in[7];
    const float* Ds        = (const float*)d_in[8];
    const float* ln_g      = (const float*)d_in[9];
    const float* ln_b      = (const float*)d_in[10];
    const float* out_w     = (const float*)d_in[11];
    float* out = (float*)d_out;

    cudaFuncSetAttribute(k_scan1<0>, cudaFuncAttributeMaxDynamicSharedMemorySize, SM1);
    cudaFuncSetAttribute(k_scan1<1>, cudaFuncAttributeMaxDynamicSharedMemorySize, SM1);
    cudaFuncSetAttribute(k_scan1<2>, cudaFuncAttributeMaxDynamicSharedMemorySize, SM1);
    cudaFuncSetAttribute(k_scan1<3>, cudaFuncAttributeMaxDynamicSharedMemorySize, SM1);
    cudaFuncSetAttribute(k_scan1<4>, cudaFuncAttributeMaxDynamicSharedMemorySize, SM1);
    cudaFuncSetAttribute(k_scan1<5>, cudaFuncAttributeMaxDynamicSharedMemorySize, SM1);
    cudaFuncSetAttribute(k_scan1<6>, cudaFuncAttributeMaxDynamicSharedMemorySize, SM1);
    cudaFuncSetAttribute(k_scan1<7>, cudaFuncAttributeMaxDynamicSharedMemorySize, SM1);
    cudaFuncSetAttribute(k_scan2<0>, cudaFuncAttributeMaxDynamicSharedMemorySize, SM3);
    cudaFuncSetAttribute(k_scan2<1>, cudaFuncAttributeMaxDynamicSharedMemorySize, SM3);
    cudaFuncSetAttribute(k_scan2<2>, cudaFuncAttributeMaxDynamicSharedMemorySize, SM3);
    cudaFuncSetAttribute(k_scan2<3>, cudaFuncAttributeMaxDynamicSharedMemorySize, SM3);
    cudaFuncSetAttribute(k_scan2<4>, cudaFuncAttributeMaxDynamicSharedMemorySize, SM3);
    cudaFuncSetAttribute(k_scan2<5>, cudaFuncAttributeMaxDynamicSharedMemorySize, SM3);
    cudaFuncSetAttribute(k_scan2<6>, cudaFuncAttributeMaxDynamicSharedMemorySize, SM3);
    cudaFuncSetAttribute(k_scan2<7>, cudaFuncAttributeMaxDynamicSharedMemorySize, SM3);
    cudaFuncSetAttribute(k_final,    cudaFuncAttributeMaxDynamicSharedMemorySize, SM4);

    k_inproj<<<L_TOT / 24, 256>>>(x, in_proj_w);
    k_conv<<<L_TOT / 4, 512>>>(conv_w, conv_b);

#define DIR_ROUND(D)                                                   \
    k_scan1<D><<<NCH, 128, SM1>>>(xproj_w, dtw, dtb, A_logs);          \
    k_prefix<<<256, 256>>>();                                          \
    k_scan2<D><<<NCH, 128, SM3>>>(A_logs, Ds);

    DIR_ROUND(0)
    DIR_ROUND(1)
    DIR_ROUND(2)
    DIR_ROUND(3)
    DIR_ROUND(4)
    DIR_ROUND(5)
    DIR_ROUND(6)
    DIR_ROUND(7)
#undef DIR_ROUND

    k_final<<<L_TOT / 16, 128, SM4>>>(ln_g, ln_b, out_w, out);
}

// round 3
// speedup vs baseline: 2.0951x; 1.1232x over previous
#include <cuda_runtime.h>
#include <math.h>

#define L_TOT 13824
#define CL    48
#define NCH   288
#define DM    128
#define NST   16
#define DTRK  8

typedef unsigned long long u64t;

// ---------------- device scratch (static, no allocations) ----------------
__device__ float g_buf[2][L_TOT * DM];   // ping-pong xc buffers [S][128]
__device__ float g_z[L_TOT * DM];        // silu(z)
__device__ float g_xp[L_TOT * DM];       // pre-conv x; reused as cumdt (seq order)
__device__ float g_y[L_TOT * DM];        // local y (seq order)
__device__ float g_dt[L_TOT * DM];       // dt, spatial order
__device__ float g_bc[L_TOT * 32];       // B(16)+C(16), spatial order
__device__ float g_Ach[NCH * 2048];      // chunk aggregate P, chunk-major [ci][d*16+n]
__device__ float g_Bch[NCH * 2048];      // chunk aggregate h_end, chunk-major
__device__ float g_Hpref[NCH * 2048];    // exclusive prefix h0, chunk-major
#define g_cumdt g_xp

__device__ __forceinline__ float siluf(float v) { return v / (1.f + __expf(-v)); }
__device__ __forceinline__ float softplusf(float x) {
    if (x > 20.f) return x;
    return __logf(1.f + __expf(x));
}

// f32x2 packed helpers (sm_100a+)
__device__ __forceinline__ u64t pk2(float lo, float hi) {
    u64t r; asm("mov.b64 %0,{%1,%2};" : "=l"(r) : "f"(lo), "f"(hi)); return r;
}
__device__ __forceinline__ void upk2(u64t v, float& lo, float& hi) {
    asm("mov.b64 {%0,%1},%2;" : "=f"(lo), "=f"(hi) : "l"(v));
}
__device__ __forceinline__ u64t mul2_(u64t a, u64t b) {
    u64t r; asm("mul.rn.f32x2 %0,%1,%2;" : "=l"(r) : "l"(a), "l"(b)); return r;
}
__device__ __forceinline__ u64t fma2_(u64t a, u64t b, u64t c) {
    u64t r; asm("fma.rn.f32x2 %0,%1,%2,%3;" : "=l"(r) : "l"(a), "l"(b), "l"(c)); return r;
}

// sequence position -> spatial index, flip folded in
template<int DIR>
__device__ __forceinline__ int seq_to_spatial(int l) {
    if (DIR & 1) l = L_TOT - 1 - l;
    int i0 = l % 24;
    int t  = l / 24;
    int i1 = t % 24;
    int i2 = t / 24;
    switch (DIR >> 1) {
        case 0:  return i1 * 576 + i2 * 24 + i0;
        case 1:  return i2 * 576 + i1 * 24 + i0;
        case 2:  return i0 * 576 + i1 * 24 + i2;
        default: return i2 * 576 + i0 * 24 + i1;
    }
}

// ---------------- K0: in_proj ----------------
__global__ void __launch_bounds__(256) k_inproj(const float* __restrict__ x,
                                                const float* __restrict__ Win) {
    const int ST = 24;
    __shared__ float xs[ST * DM];
    int s0 = blockIdx.x * ST;
    for (int j = threadIdx.x; j < ST * DM; j += 256) xs[j] = x[s0 * DM + j];
    __syncthreads();
    int e = threadIdx.x;
    float acc[ST];
#pragma unroll
    for (int i = 0; i < ST; i++) acc[i] = 0.f;
    const float4* w4 = (const float4*)(Win + e * DM);
    for (int k4 = 0; k4 < DM / 4; k4++) {
        float4 w = w4[k4];
#pragma unroll
        for (int i = 0; i < ST; i++) {
            float4 xv = *(const float4*)(xs + i * DM + k4 * 4);
            acc[i] = fmaf(w.x, xv.x, fmaf(w.y, xv.y, fmaf(w.z, xv.z, fmaf(w.w, xv.w, acc[i]))));
        }
    }
    if (e < DM) {
#pragma unroll
        for (int i = 0; i < ST; i++) g_xp[(s0 + i) * DM + e] = acc[i];
    } else {
        int c = e - DM;
#pragma unroll
        for (int i = 0; i < ST; i++) g_z[(s0 + i) * DM + c] = siluf(acc[i]);
    }
}

// ---------------- K0b: depthwise conv + silu ----------------
__global__ void __launch_bounds__(512) k_conv(const float* __restrict__ cw,
                                              const float* __restrict__ cb) {
    __shared__ float cws[DM * 27];
    int tid = threadIdx.x;
    for (int j = tid; j < DM * 27; j += 512) cws[j] = cw[j];
    __syncthreads();
    int c = tid & 127;
    int s = blockIdx.x * 4 + (tid >> 7);
    int d0 = s % 24, t = s / 24, w0 = t % 24, h0 = t / 24;
    float acc = cb[c];
#pragma unroll
    for (int kh = 0; kh < 3; kh++) {
        int hh = h0 + kh - 1; if ((unsigned)hh >= 24u) continue;
#pragma unroll
        for (int kw = 0; kw < 3; kw++) {
            int ww = w0 + kw - 1; if ((unsigned)ww >= 24u) continue;
#pragma unroll
            for (int kd = 0; kd < 3; kd++) {
                int dd = d0 + kd - 1; if ((unsigned)dd >= 24u) continue;
                acc = fmaf(cws[c * 27 + kh * 9 + kw * 3 + kd],
                           g_xp[((hh * 24 + ww) * 24 + dd) * DM + c], acc);
            }
        }
    }
    g_buf[0][s * DM + c] = siluf(acc);
}

// ---------------- Kp: projection (spatial order, full grid) --------------
// smem: xs_t[128][52] | W_s[40][129] | xd_s[40][53] | dtw_s[128][9] | bias[128]
template<int DIR>
__global__ void __launch_bounds__(256) k_proj(const float* __restrict__ xproj_w,
                                              const float* __restrict__ dtw_g,
                                              const float* __restrict__ dtb_g) {
    extern __shared__ float sm[];
    float* xs_t   = sm;                      // [128][52]
    float* W_s    = xs_t + 128 * 52;         // [40][129]
    float* xd_s   = W_s + 40 * 129;          // [40][53]
    float* dtw_s  = xd_s + 40 * 53;          // [128][9]
    float* bias_s = dtw_s + 128 * 9;         // [128]
    const int tid = threadIdx.x;
    const int s0  = blockIdx.x * 48;
    const float* __restrict__ xin = g_buf[DIR & 1];

    for (int j = tid; j < 40 * DM; j += 256)
        W_s[(j >> 7) * 129 + (j & 127)] = xproj_w[DIR * 40 * DM + j];
    for (int j = tid; j < DM * 8; j += 256)
        dtw_s[(j >> 3) * 9 + (j & 7)] = dtw_g[DIR * DM * 8 + j];
    if (tid < DM) bias_s[tid] = dtb_g[DIR * DM + tid];
    for (int j = tid; j < 48 * DM; j += 256) {
        int l = j >> 7, c = j & 127;
        xs_t[c * 52 + l] = xin[(s0 + l) * DM + c];
    }
    __syncthreads();

    if (tid < 240) {
        int f = tid % 40, lg = tid / 40, l0 = lg * 8;
        float acc[8];
#pragma unroll
        for (int i = 0; i < 8; i++) acc[i] = 0.f;
#pragma unroll 4
        for (int k = 0; k < DM; k++) {
            float w = W_s[f * 129 + k];
            float4 x0 = *(const float4*)(xs_t + k * 52 + l0);
            float4 x1 = *(const float4*)(xs_t + k * 52 + l0 + 4);
            acc[0] = fmaf(w, x0.x, acc[0]); acc[1] = fmaf(w, x0.y, acc[1]);
            acc[2] = fmaf(w, x0.z, acc[2]); acc[3] = fmaf(w, x0.w, acc[3]);
            acc[4] = fmaf(w, x1.x, acc[4]); acc[5] = fmaf(w, x1.y, acc[5]);
            acc[6] = fmaf(w, x1.z, acc[6]); acc[7] = fmaf(w, x1.w, acc[7]);
        }
#pragma unroll
        for (int i = 0; i < 8; i++) xd_s[f * 53 + l0 + i] = acc[i];
    }
    __syncthreads();

    // dt = softplus(dtw @ xd[0:8] + bias)
    for (int j = tid; j < 48 * DM; j += 256) {
        int l = j >> 7, d = j & 127;
        float a = bias_s[d];
#pragma unroll
        for (int r = 0; r < 8; r++) a = fmaf(dtw_s[d * 9 + r], xd_s[r * 53 + l], a);
        g_dt[(s0 + l) * DM + d] = softplusf(a);
    }
    // bc = xd[8:40]
    for (int j = tid; j < 48 * 32; j += 256) {
        int l = j >> 5, n = j & 31;
        g_bc[(s0 + l) * 32 + n] = xd_s[(8 + n) * 53 + l];
    }
}

// ---------------- Ks: chunk-local scan, emits y_local + cumdt ------------
// smem: u_s[128][49] | dt_s[128][49] | bc_s[48][32]
template<int DIR>
__global__ void __launch_bounds__(128) k_scan(const float* __restrict__ Alog_g,
                                              const float* __restrict__ Ds_g) {
    extern __shared__ float sm[];
    float* u_s  = sm;                 // [128][49]
    float* dt_s = sm + 128 * 49;      // [128][49]
    float* bc_s = dt_s + 128 * 49;    // [48][32]
    const int tid = threadIdx.x;
    const int ci  = blockIdx.x;
    const int lbase = ci * CL;
    const float* __restrict__ xin = g_buf[DIR & 1];

#pragma unroll 4
    for (int l = 0; l < CL; l++) {
        int sp = seq_to_spatial<DIR>(lbase + l);
        u_s[tid * 49 + l]  = xin[sp * DM + tid];
        dt_s[tid * 49 + l] = g_dt[sp * DM + tid];
    }
    for (int j = tid; j < CL * 32; j += 128) {
        int l = j >> 5, n = j & 31;
        bc_s[j] = g_bc[seq_to_spatial<DIR>(lbase + l) * 32 + n];
    }
    __syncthreads();

    float A_[NST];
#pragma unroll
    for (int n = 0; n < NST; n++) A_[n] = -__expf(Alog_g[(DIR * DM + tid) * NST + n]);
    float A0 = A_[0];
    bool fast = true;
#pragma unroll
    for (int n = 0; n < NST; n++)
        if (fabsf(A_[n] - (float)(n + 1) * A0) > 1e-5f * fabsf(A_[n])) fast = false;
    float Dv = Ds_g[DIR * DM + tid];

    float cum = 0.f;
    float hv[NST];

    if (fast) {
        u64t h2[8];
#pragma unroll
        for (int k = 0; k < 8; k++) h2[k] = 0ull;
        for (int l = 0; l < CL; l++) {
            float dt = dt_s[tid * 49 + l];
            float u  = u_s[tid * 49 + l];
            cum += dt;
            float e1 = __expf(A0 * dt);
            float e2 = e1 * e1;
            u64t e22 = pk2(e2, e2);
            u64t av  = pk2(e1, e2);
            float dtu = dt * u;
            u64t dtu2 = pk2(dtu, dtu);
            u64t y2 = 0ull;
#pragma unroll
            for (int k = 0; k < 8; k++) {
                if (k) av = mul2_(av, e22);
                u64t B2 = *(const u64t*)(bc_s + l * 32 + 2 * k);
                u64t C2 = *(const u64t*)(bc_s + l * 32 + 16 + 2 * k);
                h2[k] = fma2_(av, h2[k], mul2_(dtu2, B2));
                y2 = fma2_(h2[k], C2, y2);
            }
            float ylo, yhi; upk2(y2, ylo, yhi);
            float y = fmaf(u, Dv, ylo + yhi);
            g_y[(lbase + l) * DM + tid]     = y;
            g_cumdt[(lbase + l) * DM + tid] = cum;
        }
#pragma unroll
        for (int k = 0; k < 8; k++) upk2(h2[k], hv[2 * k], hv[2 * k + 1]);
    } else {
        float h[NST];
#pragma unroll
        for (int n = 0; n < NST; n++) h[n] = 0.f;
        for (int l = 0; l < CL; l++) {
            float dt = dt_s[tid * 49 + l];
            float u  = u_s[tid * 49 + l];
            cum += dt;
            float dtu = dt * u;
            float y = u * Dv;
#pragma unroll
            for (int n = 0; n < NST; n++) {
                h[n] = fmaf(__expf(A_[n] * dt), h[n], dtu * bc_s[l * 32 + n]);
                y = fmaf(h[n], bc_s[l * 32 + 16 + n], y);
            }
            g_y[(lbase + l) * DM + tid]     = y;
            g_cumdt[(lbase + l) * DM + tid] = cum;
        }
#pragma unroll
        for (int n = 0; n < NST; n++) hv[n] = h[n];
    }

    // chunk aggregates, chunk-major (coalesced float4)
    float P[NST];
#pragma unroll
    for (int n = 0; n < NST; n++) P[n] = __expf(A_[n] * cum);
    float4* pa = (float4*)(g_Ach + ci * 2048 + tid * 16);
    float4* pb = (float4*)(g_Bch + ci * 2048 + tid * 16);
#pragma unroll
    for (int q = 0; q < 4; q++) {
        pa[q] = make_float4(P[4 * q], P[4 * q + 1], P[4 * q + 2], P[4 * q + 3]);
        pb[q] = make_float4(hv[4 * q], hv[4 * q + 1], hv[4 * q + 2], hv[4 * q + 3]);
    }
}

// ---------------- Kprefix: transposed warp-scan over chunk aggregates ----
// grid 256 x 256 threads; block handles 8 (d,n) rows via smem transpose
__global__ void __launch_bounds__(256) k_prefix() {
    __shared__ float Aa_s[NCH * 9], Bb_s[NCH * 9], Hp_s[NCH * 9];
    const int tid = threadIdx.x;
    const int gw0 = blockIdx.x * 8;
    for (int j = tid; j < NCH * 8; j += 256) {
        int c = j >> 3, w = j & 7;
        Aa_s[c * 9 + w] = g_Ach[c * 2048 + gw0 + w];
        Bb_s[c * 9 + w] = g_Bch[c * 2048 + gw0 + w];
    }
    __syncthreads();
    int w = tid >> 5, lane = tid & 31;
    float a_loc[9], b_loc[9];
    float Ag = 1.f, Bg = 0.f;
    int c0 = lane * 9;
#pragma unroll
    for (int k = 0; k < 9; k++) {
        float a = Aa_s[(c0 + k) * 9 + w];
        float b = Bb_s[(c0 + k) * 9 + w];
        a_loc[k] = a; b_loc[k] = b;
        Bg = fmaf(a, Bg, b);
        Ag *= a;
    }
#pragma unroll
    for (int d = 1; d < 32; d <<= 1) {
        float aL = __shfl_up_sync(0xffffffffu, Ag, d);
        float bL = __shfl_up_sync(0xffffffffu, Bg, d);
        if (lane >= d) { Bg = fmaf(Ag, bL, Bg); Ag *= aL; }
    }
    float hp = __shfl_up_sync(0xffffffffu, Bg, 1);
    float h = (lane == 0) ? 0.f : hp;
#pragma unroll
    for (int k = 0; k < 9; k++) {
        Hp_s[(c0 + k) * 9 + w] = h;
        h = fmaf(a_loc[k], h, b_loc[k]);
    }
    __syncthreads();
    for (int j = tid; j < NCH * 8; j += 256) {
        int c = j >> 3, wq = j & 7;
        g_Hpref[c * 2048 + gw0 + wq] = Hp_s[c * 9 + wq];
    }
}

// ---------------- Kc: parallel correction + scatter ----------------------
// block = 24 positions (half chunk), 128 threads; grid 576
template<int DIR>
__global__ void __launch_bounds__(128) k_corr(const float* __restrict__ Alog_g) {
    __shared__ float C_s[24 * 18];
    const int tid = threadIdx.x;
    const int L0 = blockIdx.x * 24;
    const int ci = blockIdx.x >> 1;
    float* __restrict__ xout = g_buf[(DIR + 1) & 1];

    for (int j = tid; j < 24 * 16; j += 128) {
        int l = j >> 4, n = j & 15;
        C_s[l * 18 + n] = g_bc[seq_to_spatial<DIR>(L0 + l) * 32 + 16 + n];
    }
    __syncthreads();

    float A_[NST];
#pragma unroll
    for (int n = 0; n < NST; n++) A_[n] = -__expf(Alog_g[(DIR * DM + tid) * NST + n]);
    float A0 = A_[0];
    bool fast = true;
#pragma unroll
    for (int n = 0; n < NST; n++)
        if (fabsf(A_[n] - (float)(n + 1) * A0) > 1e-5f * fabsf(A_[n])) fast = false;

    float h0[NST];
    const float4* hp4 = (const float4*)(g_Hpref + ci * 2048 + tid * 16);
#pragma unroll
    for (int q = 0; q < 4; q++) {
        float4 v = hp4[q];
        h0[4 * q] = v.x; h0[4 * q + 1] = v.y; h0[4 * q + 2] = v.z; h0[4 * q + 3] = v.w;
    }

    if (fast) {
        u64t h0p[8];
#pragma unroll
        for (int k = 0; k < 8; k++) h0p[k] = pk2(h0[2 * k], h0[2 * k + 1]);
#pragma unroll 2
        for (int l = 0; l < 24; l++) {
            int idx = (L0 + l) * DM + tid;
            float cumv = g_cumdt[idx];
            float y    = g_y[idx];
            float e1 = __expf(A0 * cumv);
            float e2 = e1 * e1;
            u64t e22 = pk2(e2, e2);
            u64t av  = pk2(e1, e2);
            u64t acc = 0ull;
#pragma unroll
            for (int k = 0; k < 8; k++) {
                if (k) av = mul2_(av, e22);
                u64t C2 = *(const u64t*)(C_s + l * 18 + 2 * k);
                acc = fma2_(mul2_(h0p[k], av), C2, acc);
            }
            float lo, hi; upk2(acc, lo, hi);
            xout[seq_to_spatial<DIR>(L0 + l) * DM + tid] = y + lo + hi;
        }
    } else {
        for (int l = 0; l < 24; l++) {
            int idx = (L0 + l) * DM + tid;
            float cumv = g_cumdt[idx];
            float y    = g_y[idx];
#pragma unroll
            for (int n = 0; n < NST; n++)
                y = fmaf(h0[n] * __expf(A_[n] * cumv), C_s[l * 18 + n], y);
            xout[seq_to_spatial<DIR>(L0 + l) * DM + tid] = y;
        }
    }
}

// ---------------- K4: LayerNorm + gate + out_proj ------------------------
__global__ void __launch_bounds__(128) k_final(const float* __restrict__ gamma,
                                               const float* __restrict__ beta,
                                               const float* __restrict__ Wout,
                                               float* __restrict__ out) {
    extern __shared__ float sm[];
    float* ym = sm;                   // [16][132]
    float* Wt = sm + 16 * 132;        // [128][129]
    __shared__ float mu_s[16], rs_s[16];
    const int tid = threadIdx.x;
    const int s0 = blockIdx.x * 16;

    for (int j = tid; j < 16 * DM; j += 128) {
        int si = j >> 7, c = j & 127;
        ym[si * 132 + c] = g_buf[0][(s0 + si) * DM + c];
    }
    for (int j = tid; j < DM * DM; j += 128) {
        int c = j >> 7, e = j & 127;
        Wt[e * 129 + c] = Wout[j];
    }
    __syncthreads();

    if (tid < 16) {
        float m = 0.f;
        for (int c = 0; c < DM; c++) m += ym[tid * 132 + c];
        m *= (1.f / DM);
        float v = 0.f;
        for (int c = 0; c < DM; c++) { float d = ym[tid * 132 + c] - m; v = fmaf(d, d, v); }
        v *= (1.f / DM);
        mu_s[tid] = m;
        rs_s[tid] = rsqrtf(v + 1e-5f);
    }
    __syncthreads();

    for (int j = tid; j < 16 * DM; j += 128) {
        int si = j >> 7, c = j & 127;
        float v = (ym[si * 132 + c] - mu_s[si]) * rs_s[si] * gamma[c] + beta[c];
        ym[si * 132 + c] = v * g_z[(s0 + si) * DM + c];
    }
    __syncthreads();

    float acc[16];
#pragma unroll
    for (int i = 0; i < 16; i++) acc[i] = 0.f;
    for (int e4 = 0; e4 < DM / 4; e4++) {
        float w0 = Wt[(e4 * 4 + 0) * 129 + tid];
        float w1 = Wt[(e4 * 4 + 1) * 129 + tid];
        float w2 = Wt[(e4 * 4 + 2) * 129 + tid];
        float w3 = Wt[(e4 * 4 + 3) * 129 + tid];
#pragma unroll
        for (int si = 0; si < 16; si++) {
            float4 yv = *(const float4*)(ym + si * 132 + e4 * 4);
            acc[si] = fmaf(w0, yv.x, fmaf(w1, yv.y, fmaf(w2, yv.z, fmaf(w3, yv.w, acc[si]))));
        }
    }
#pragma unroll
    for (int si = 0; si < 16; si++) out[(s0 + si) * DM + tid] = acc[si];
}

// ---------------- launch ----------------
#define SMP ((128 * 52 + 40 * 129 + 40 * 53 + 128 * 9 + 128) * 4)
#define SMS ((128 * 49 * 2 + 48 * 32) * 4)
#define SM4 ((16 * 132 + 128 * 129) * 4)

extern "C" void kernel_launch(void* const* d_in, const int* in_sizes, int n_in,
                              void* d_out, int out_size) {
    const float* x         = (const float*)d_in[0];
    const float* in_proj_w = (const float*)d_in[1];
    const float* conv_w    = (const float*)d_in[2];
    const float* conv_b    = (const float*)d_in[3];
    const float* xproj_w   = (const float*)d_in[4];
    const float* dtw       = (const float*)d_in[5];
    const float* dtb       = (const float*)d_in[6];
    const float* A_logs    = (const float*)d_in[7];
    const float* Ds        = (const float*)d_in[8];
    const float* ln_g      = (const float*)d_in[9];
    const float* ln_b      = (const float*)d_in[10];
    const float* out_w     = (const float*)d_in[11];
    float* out = (float*)d_out;

#define SETA(K, S) cudaFuncSetAttribute(K, cudaFuncAttributeMaxDynamicSharedMemorySize, S)
    SETA(k_proj<0>, SMP); SETA(k_proj<1>, SMP); SETA(k_proj<2>, SMP); SETA(k_proj<3>, SMP);
    SETA(k_proj<4>, SMP); SETA(k_proj<5>, SMP); SETA(k_proj<6>, SMP); SETA(k_proj<7>, SMP);
    SETA(k_scan<0>, SMS); SETA(k_scan<1>, SMS); SETA(k_scan<2>, SMS); SETA(k_scan<3>, SMS);
    SETA(k_scan<4>, SMS); SETA(k_scan<5>, SMS); SETA(k_scan<6>, SMS); SETA(k_scan<7>, SMS);
    SETA(k_final, SM4);
#undef SETA

    k_inproj<<<L_TOT / 24, 256>>>(x, in_proj_w);
    k_conv<<<L_TOT / 4, 512>>>(conv_w, conv_b);

#define DIR_ROUND(D)                                           \
    k_proj<D><<<NCH, 256, SMP>>>(xproj_w, dtw, dtb);           \
    k_scan<D><<<NCH, 128, SMS>>>(A_logs, Ds);                  \
    k_prefix<<<256, 256>>>();                                  \
    k_corr<D><<<L_TOT / 24, 128>>>(A_logs);

    DIR_ROUND(0)
    DIR_ROUND(1)
    DIR_ROUND(2)
    DIR_ROUND(3)
    DIR_ROUND(4)
    DIR_ROUND(5)
    DIR_ROUND(6)
    DIR_ROUND(7)
#undef DIR_ROUND

    k_final<<<L_TOT / 16, 128, SM4>>>(ln_g, ln_b, out_w, out);
}